// round 12
// baseline (speedup 1.0000x reference)
#include <cuda_runtime.h>
#include <cstdint>

#define MAX_BLOCKS 2048
__device__ float        g_partials[MAX_BLOCKS];
__device__ unsigned int g_ticket;          // 0 at load; last block resets to 0 each launch

// cp.async helpers (16B, .cg)
__device__ __forceinline__ void cp_async16(uint32_t smem_addr, const void* gptr, bool pred) {
    asm volatile(
        "{\n\t.reg .pred p;\n\t"
        "setp.ne.b32 p, %0, 0;\n\t"
        "@p cp.async.cg.shared.global [%1], [%2], 16;\n\t}"
        :: "r"((int)pred), "r"(smem_addr), "l"(gptr));
}
#define CP_COMMIT()  asm volatile("cp.async.commit_group;" ::: "memory")
#define CP_WAIT(n)   asm volatile("cp.async.wait_group %0;" :: "n"(n) : "memory")

// ---------------------------------------------------------------------------
// Loss = 0.5 * sum( (outputs - psp(target))^2 ), psp = leaky integrator over
// contiguous trailing axis T. Fast path (T%4==0, T/4<=26):
//   BLOCK-staged pipeline: each block stages 16-pixel tiles of both tensors
//   into smem via cp.async. Tile = 16*400B = 50 exact 128B lines -> global
//   loads are perfectly aligned/dense (minimal sectors+wavefronts per byte),
//   independent of the scan's 400B-row layout. Warps read their 2 rows from
//   smem and run the interleaved Kogge-Stone scan. 3 stages, 2 barriers/iter.
// Last-block reduction; single launch.
// ---------------------------------------------------------------------------
#define TILE_PIX     16
#define NSTAGE       3
#define MAX_ROWB     416                          // supports T <= 104
#define STAGE_STRIDE (TILE_PIX * MAX_ROWB * 2)    // 13312 B
#define MAX_TV       26

__global__ void __launch_bounds__(256) spike_loss_kernel(
    const float* __restrict__ outputs,
    const float* __restrict__ target,
    const int* __restrict__ n_steps_p,
    const int* __restrict__ tau_p,
    long long n_total,
    float* __restrict__ out)
{
    __shared__ __align__(16) char buf[NSTAGE * STAGE_STRIDE];   // 39936 B

    const int   T       = *n_steps_p;
    const float tau     = (float)(*tau_p);
    const float inv_tau = 1.0f / tau;
    const float decay   = 1.0f - inv_tau;

    const int tid  = threadIdx.x;
    const int lane = tid & 31;
    const int wib  = tid >> 5;
    const unsigned FULL = 0xffffffffu;

    const long long pixels      = n_total / (long long)T;
    const int       warps_total = (gridDim.x * blockDim.x) >> 5;
    const int       warp_id     = (int)((blockIdx.x * blockDim.x + tid) >> 5);

    float acc = 0.0f;

    if ((T & 3) == 0 && (T >> 2) <= MAX_TV) {
        // ============ fast path: block-staged aligned cp.async ============
        const int TV    = T >> 2;
        const int rowB  = T * 4;                 // 400 for T=100
        const int halfB = TILE_PIX * rowB;       // target half size per stage
        const int cnt16 = (2 * halfB) >> 4;      // 16B chunks per stage

        const float w1 = decay;
        const float w2 = decay * decay;
        const float w3 = w2 * decay;
        const float q  = w2 * w2;                // decay^4 (warp-scan ratio)
        const float q1  = q;
        const float q2  = q1 * q1;
        const float q4  = q2 * q2;
        const float q8  = q4 * q4;
        const float q16 = q8 * q8;

        const bool vl = (lane < TV);
        const float4 z = make_float4(0.f, 0.f, 0.f, 0.f);

        const long long ntiles = (pixels + TILE_PIX - 1) / TILE_PIX;
        const uint32_t  sbase  = (uint32_t)__cvta_generic_to_shared(buf);

        auto issue_stage = [&](long long tile, int s) {
            const uint32_t st = sbase + s * STAGE_STRIDE;
            const long long tb = tile * TILE_PIX;             // first pixel of tile
            int validB = 0;
            const char* tg = nullptr;
            const char* ob = nullptr;
            if (tb < pixels) {
                long long vp = pixels - tb;
                if (vp > TILE_PIX) vp = TILE_PIX;
                validB = (int)vp * rowB;
                tg = (const char*)(target  + tb * (long long)T);
                ob = (const char*)(outputs + tb * (long long)T);
            }
            for (int i = tid; i < cnt16; i += 256) {
                const int  off  = i << 4;
                const bool isT  = (off < halfB);
                const int  loff = isT ? off : off - halfB;
                const bool pred = (loff < validB);
                const char* src = (isT ? tg : ob) + loff;
                cp_async16(st + off, src, pred);
            }
            CP_COMMIT();
        };

        const long long tile0 = blockIdx.x;
        #pragma unroll
        for (int s = 0; s < NSTAGE; ++s)
            issue_stage(tile0 + (long long)s * gridDim.x, s);

        float accA = 0.0f, accB = 0.0f;
        int stage = 0;
        for (long long tile = tile0; tile < ntiles; tile += gridDim.x) {
            CP_WAIT(NSTAGE - 1);
            __syncthreads();                      // all threads' stage copies visible

            const char* st  = buf + stage * STAGE_STRIDE;
            const long long pA = tile * TILE_PIX + 2 * wib;
            const bool hasA = (pA     < pixels);
            const bool hasB = (pA + 1 < pixels);
            const char* tgA = st + (2 * wib) * rowB;
            const char* obA = st + halfB + (2 * wib) * rowB;
            const int lo = lane * 16;

            float4 xA = (vl && hasA) ? *(const float4*)(tgA        + lo) : z;
            float4 xB = (vl && hasB) ? *(const float4*)(tgA + rowB + lo) : z;
            float4 oA = (vl && hasA) ? *(const float4*)(obA        + lo) : z;
            float4 oB = (vl && hasB) ? *(const float4*)(obA + rowB + lo) : z;

            __syncthreads();                      // everyone done reading this stage
            issue_stage(tile + (long long)NSTAGE * gridDim.x, stage);   // refill (overlaps scan)

            // local 4-elem inclusive scans (two independent chains)
            float a0 = xA.x,                  b0 = xB.x;
            float a1 = fmaf(decay, a0, xA.y), b1 = fmaf(decay, b0, xB.y);
            float a2 = fmaf(decay, a1, xA.z), b2 = fmaf(decay, b1, xB.z);
            float a3 = fmaf(decay, a2, xA.w), b3 = fmaf(decay, b2, xB.w);

            // interleaved Kogge-Stone warp scans of lane carries (ratio q)
            float cA = vl ? a3 : 0.0f;
            float cB = vl ? b3 : 0.0f;
            float u, v;
            u = __shfl_up_sync(FULL, cA, 1);  v = __shfl_up_sync(FULL, cB, 1);
            if (lane >= 1)  { cA = fmaf(q1,  u, cA); cB = fmaf(q1,  v, cB); }
            u = __shfl_up_sync(FULL, cA, 2);  v = __shfl_up_sync(FULL, cB, 2);
            if (lane >= 2)  { cA = fmaf(q2,  u, cA); cB = fmaf(q2,  v, cB); }
            u = __shfl_up_sync(FULL, cA, 4);  v = __shfl_up_sync(FULL, cB, 4);
            if (lane >= 4)  { cA = fmaf(q4,  u, cA); cB = fmaf(q4,  v, cB); }
            u = __shfl_up_sync(FULL, cA, 8);  v = __shfl_up_sync(FULL, cB, 8);
            if (lane >= 8)  { cA = fmaf(q8,  u, cA); cB = fmaf(q8,  v, cB); }
            u = __shfl_up_sync(FULL, cA, 16); v = __shfl_up_sync(FULL, cB, 16);
            if (lane >= 16) { cA = fmaf(q16, u, cA); cB = fmaf(q16, v, cB); }

            // exclusive prefixes (single chunk: no cross-chunk carry)
            float prefA = __shfl_up_sync(FULL, cA, 1);
            float prefB = __shfl_up_sync(FULL, cB, 1);
            if (lane == 0) { prefA = 0.0f; prefB = 0.0f; }

            a0 = fmaf(prefA, w1, a0);  b0 = fmaf(prefB, w1, b0);
            a1 = fmaf(prefA, w2, a1);  b1 = fmaf(prefB, w2, b1);
            a2 = fmaf(prefA, w3, a2);  b2 = fmaf(prefB, w3, b2);
            a3 = fmaf(prefA, q,  a3);  b3 = fmaf(prefB, q,  b3);

            if (vl) {
                float e0 = oA.x - a0 * inv_tau;
                float e1 = oA.y - a1 * inv_tau;
                float e2 = oA.z - a2 * inv_tau;
                float e3 = oA.w - a3 * inv_tau;
                accA = fmaf(e0, e0, accA);
                accA = fmaf(e1, e1, accA);
                accA = fmaf(e2, e2, accA);
                accA = fmaf(e3, e3, accA);

                float f0 = oB.x - b0 * inv_tau;
                float f1 = oB.y - b1 * inv_tau;
                float f2 = oB.z - b2 * inv_tau;
                float f3 = oB.w - b3 * inv_tau;
                accB = fmaf(f0, f0, accB);
                accB = fmaf(f1, f1, accB);
                accB = fmaf(f2, f2, accB);
                accB = fmaf(f3, f3, accB);
            }

            if (++stage == NSTAGE) stage = 0;
        }
        CP_WAIT(0);                               // drain before exit
        acc = accA + accB;

    } else if ((T & 3) == 0) {
        // ============ general float4 path (TV > MAX_TV) ============
        const int TV = T >> 2;
        const float w1 = decay;
        const float w2 = decay * decay;
        const float w3 = w2 * decay;
        const float q  = w2 * w2;
        const float q1  = q;
        const float q2  = q1 * q1;
        const float q4  = q2 * q2;
        const float q8  = q4 * q4;
        const float q16 = q8 * q8;
        const float qlane = __powf(q, (float)lane);

        const long long stride2 = (long long)warps_total * 2;
        for (long long p = (long long)warp_id * 2; p < pixels; p += stride2) {
            const bool hasB = (p + 1 < pixels);
            const float4* tg = (const float4*)(target  + p * (long long)T);
            const float4* ob = (const float4*)(outputs + p * (long long)T);

            float carryA = 0.0f, carryB = 0.0f;
            for (int c4 = 0; c4 < TV; c4 += 32) {
                const int  l4     = c4 + lane;
                const bool validA = (l4 < TV);
                const bool validB = validA && hasB;
                const bool more   = (c4 + 32 < TV);
                const int  last   = more ? 31 : (TV - c4 - 1);

                const float4 z = make_float4(0.f, 0.f, 0.f, 0.f);
                float4 xA = validA ? tg[l4]      : z;
                float4 oA = validA ? ob[l4]      : z;
                float4 xB = validB ? tg[l4 + TV] : z;
                float4 oB = validB ? ob[l4 + TV] : z;

                float a0 = xA.x,                  b0 = xB.x;
                float a1 = fmaf(decay, a0, xA.y), b1 = fmaf(decay, b0, xB.y);
                float a2 = fmaf(decay, a1, xA.z), b2 = fmaf(decay, b1, xB.z);
                float a3 = fmaf(decay, a2, xA.w), b3 = fmaf(decay, b2, xB.w);

                float cA = validA ? a3 : 0.0f;
                float cB = validB ? b3 : 0.0f;
                float u, v;
                u = __shfl_up_sync(FULL, cA, 1);  v = __shfl_up_sync(FULL, cB, 1);
                if (lane >= 1)  { cA = fmaf(q1,  u, cA); cB = fmaf(q1,  v, cB); }
                u = __shfl_up_sync(FULL, cA, 2);  v = __shfl_up_sync(FULL, cB, 2);
                if (lane >= 2)  { cA = fmaf(q2,  u, cA); cB = fmaf(q2,  v, cB); }
                u = __shfl_up_sync(FULL, cA, 4);  v = __shfl_up_sync(FULL, cB, 4);
                if (lane >= 4)  { cA = fmaf(q4,  u, cA); cB = fmaf(q4,  v, cB); }
                u = __shfl_up_sync(FULL, cA, 8);  v = __shfl_up_sync(FULL, cB, 8);
                if (lane >= 8)  { cA = fmaf(q8,  u, cA); cB = fmaf(q8,  v, cB); }
                u = __shfl_up_sync(FULL, cA, 16); v = __shfl_up_sync(FULL, cB, 16);
                if (lane >= 16) { cA = fmaf(q16, u, cA); cB = fmaf(q16, v, cB); }

                float prefA = __shfl_up_sync(FULL, cA, 1);
                float prefB = __shfl_up_sync(FULL, cB, 1);
                if (lane == 0) { prefA = 0.0f; prefB = 0.0f; }
                prefA = fmaf(carryA, qlane, prefA);
                prefB = fmaf(carryB, qlane, prefB);

                a0 = fmaf(prefA, w1, a0);  b0 = fmaf(prefB, w1, b0);
                a1 = fmaf(prefA, w2, a1);  b1 = fmaf(prefB, w2, b1);
                a2 = fmaf(prefA, w3, a2);  b2 = fmaf(prefB, w3, b2);
                a3 = fmaf(prefA, q,  a3);  b3 = fmaf(prefB, q,  b3);

                if (validA) {
                    float e0 = oA.x - a0 * inv_tau;
                    float e1 = oA.y - a1 * inv_tau;
                    float e2 = oA.z - a2 * inv_tau;
                    float e3 = oA.w - a3 * inv_tau;
                    acc = fmaf(e0, e0, acc); acc = fmaf(e1, e1, acc);
                    acc = fmaf(e2, e2, acc); acc = fmaf(e3, e3, acc);
                }
                if (validB) {
                    float e0 = oB.x - b0 * inv_tau;
                    float e1 = oB.y - b1 * inv_tau;
                    float e2 = oB.z - b2 * inv_tau;
                    float e3 = oB.w - b3 * inv_tau;
                    acc = fmaf(e0, e0, acc); acc = fmaf(e1, e1, acc);
                    acc = fmaf(e2, e2, acc); acc = fmaf(e3, e3, acc);
                }
                if (more) {
                    carryA = __shfl_sync(FULL, a3, last);
                    carryB = __shfl_sync(FULL, b3, last);
                }
            }
        }
    } else {
        // ============ generic scalar fallback ============
        const float d1  = decay;
        const float d2  = d1 * d1;
        const float d4  = d2 * d2;
        const float d8  = d4 * d4;
        const float d16 = d8 * d8;
        const float dlane1 = __powf(decay, (float)(lane + 1));

        for (long long p = warp_id; p < pixels; p += warps_total) {
            const float* tg = target  + p * (long long)T;
            const float* ob = outputs + p * (long long)T;
            float carry = 0.0f;
            for (int t0 = 0; t0 < T; t0 += 32) {
                const int  t     = t0 + lane;
                const bool valid = (t < T);
                float x = valid ? tg[t] : 0.0f;
                float o = valid ? ob[t] : 0.0f;
                float syn = x, v;
                v = __shfl_up_sync(FULL, syn, 1);  if (lane >= 1)  syn = fmaf(d1,  v, syn);
                v = __shfl_up_sync(FULL, syn, 2);  if (lane >= 2)  syn = fmaf(d2,  v, syn);
                v = __shfl_up_sync(FULL, syn, 4);  if (lane >= 4)  syn = fmaf(d4,  v, syn);
                v = __shfl_up_sync(FULL, syn, 8);  if (lane >= 8)  syn = fmaf(d8,  v, syn);
                v = __shfl_up_sync(FULL, syn, 16); if (lane >= 16) syn = fmaf(d16, v, syn);
                syn = fmaf(carry, dlane1, syn);
                if (valid) {
                    const float d = o - syn * inv_tau;
                    acc = fmaf(d, d, acc);
                }
                carry = __shfl_sync(FULL, syn, 31);
            }
        }
    }

    // ---- block reduction of acc ----
    #pragma unroll
    for (int off = 16; off; off >>= 1)
        acc += __shfl_down_sync(FULL, acc, off);

    __shared__ float warp_sums[8];
    __shared__ bool  s_is_last;
    if (lane == 0) warp_sums[wib] = acc;
    __syncthreads();

    if (threadIdx.x == 0) {
        const int nw = blockDim.x >> 5;
        float s = 0.0f;
        #pragma unroll
        for (int i = 0; i < 8; i++)
            if (i < nw) s += warp_sums[i];
        g_partials[blockIdx.x] = s;
        __threadfence();
        unsigned old = atomicAdd(&g_ticket, 1u);
        s_is_last = (old == gridDim.x - 1);
    }
    __syncthreads();

    if (s_is_last) {
        volatile float* parts = g_partials;
        double s = 0.0;
        for (int i = threadIdx.x; i < (int)gridDim.x; i += blockDim.x)
            s += (double)parts[i];
        #pragma unroll
        for (int off = 16; off; off >>= 1)
            s += __shfl_down_sync(FULL, s, off);

        __shared__ double dsums[8];
        if (lane == 0) dsums[wib] = s;
        __syncthreads();
        if (threadIdx.x == 0) {
            const int nw = blockDim.x >> 5;
            double t = 0.0;
            #pragma unroll
            for (int i = 0; i < 8; i++)
                if (i < nw) t += dsums[i];
            out[0] = (float)(0.5 * t);
            g_ticket = 0;
        }
    }
}

extern "C" void kernel_launch(void* const* d_in, const int* in_sizes, int n_in,
                              void* d_out, int out_size)
{
    const float* outputs = (const float*)d_in[0];
    const float* target  = (const float*)d_in[1];
    const int*   n_steps = (const int*)d_in[2];
    const int*   tau_s   = (const int*)d_in[3];
    float*       out     = (float*)d_out;

    const long long n_total = (long long)in_sizes[0];

    const int threads = 256;
    const int blocks  = 148 * 8;   // 1184 <= MAX_BLOCKS
    spike_loss_kernel<<<blocks, threads>>>(outputs, target, n_steps, tau_s, n_total, out);
}

// round 13
// speedup vs baseline: 1.0332x; 1.0332x over previous
#include <cuda_runtime.h>

#define MAX_BLOCKS 2048
__device__ float        g_partials[MAX_BLOCKS];
__device__ unsigned int g_ticket;          // 0 at load; last block resets to 0 each launch

// ---------------------------------------------------------------------------
// Loss = 0.5 * sum( (outputs - psp(target))^2 ), psp = leaky integrator over
// contiguous trailing axis T. One warp per pixel pair (lane l owns float4 of
// t=4l..4l+3); 2 adjacent pixels per warp iteration. Fast path for TV<=32:
// single straight-line chunk, software-pipelined p-loop (next iteration's
// target rows prefetched before the current scan). All global loads use
// __ldcs (evict-first streaming: data is read exactly once). R12 evidence:
// three different staging architectures all pin DRAM at ~73% — this is the
// platform ceiling for the stream, so the structure is frozen at the best
// variant (R8). Last-block reduction; single launch.
// ---------------------------------------------------------------------------
__global__ void __launch_bounds__(256, 4) spike_loss_kernel(
    const float* __restrict__ outputs,
    const float* __restrict__ target,
    const int* __restrict__ n_steps_p,
    const int* __restrict__ tau_p,
    long long n_total,
    float* __restrict__ out)
{
    const int   T       = *n_steps_p;
    const float tau     = (float)(*tau_p);
    const float inv_tau = 1.0f / tau;
    const float decay   = 1.0f - inv_tau;

    const int lane = threadIdx.x & 31;
    const unsigned FULL = 0xffffffffu;

    const long long pixels      = n_total / (long long)T;
    const int       warps_total = (gridDim.x * blockDim.x) >> 5;
    const int       warp_id     = (int)((blockIdx.x * blockDim.x + threadIdx.x) >> 5);

    float acc = 0.0f;

    if ((T & 3) == 0 && (T >> 2) <= 32) {
        // ============ fast path: TV <= 32, single chunk, pipelined ============
        const int TV = T >> 2;

        const float w1 = decay;
        const float w2 = decay * decay;
        const float w3 = w2 * decay;
        const float q  = w2 * w2;              // decay^4 (warp-scan ratio)
        const float q1  = q;
        const float q2  = q1 * q1;
        const float q4  = q2 * q2;
        const float q8  = q4 * q4;
        const float q16 = q8 * q8;

        const float4 z = make_float4(0.f, 0.f, 0.f, 0.f);
        const bool   vl = (lane < TV);
        const long long stride2 = (long long)warps_total * 2;

        float accA = 0.0f, accB = 0.0f;

        long long p = (long long)warp_id * 2;

        // prologue: preload target rows for first iteration (streaming loads)
        float4 xA = z, xB = z;
        if (p < pixels) {
            const float4* tg = (const float4*)(target + p * (long long)T);
            const bool hasB0 = (p + 1 < pixels);
            if (vl)          xA = __ldcs(tg + lane);
            if (vl && hasB0) xB = __ldcs(tg + lane + TV);
        }

        for (; p < pixels; p += stride2) {
            const bool hasB = (p + 1 < pixels);

            // outputs for current iteration: consumed only at the loss (big slack)
            const float4* ob = (const float4*)(outputs + p * (long long)T);
            float4 oA = vl           ? __ldcs(ob + lane)      : z;
            float4 oB = (vl && hasB) ? __ldcs(ob + lane + TV) : z;

            // prefetch target rows for NEXT iteration (overlaps the scan below)
            const long long pn = p + stride2;
            float4 nxA = z, nxB = z;
            if (pn < pixels) {
                const float4* tgn = (const float4*)(target + pn * (long long)T);
                const bool hasBn = (pn + 1 < pixels);
                if (vl)          nxA = __ldcs(tgn + lane);
                if (vl && hasBn) nxB = __ldcs(tgn + lane + TV);
            }

            // local 4-elem inclusive scans (two independent chains)
            float a0 = xA.x,                  b0 = xB.x;
            float a1 = fmaf(decay, a0, xA.y), b1 = fmaf(decay, b0, xB.y);
            float a2 = fmaf(decay, a1, xA.z), b2 = fmaf(decay, b1, xB.z);
            float a3 = fmaf(decay, a2, xA.w), b3 = fmaf(decay, b2, xB.w);

            // interleaved Kogge-Stone warp scans of lane carries (ratio q)
            float cA = vl ? a3 : 0.0f;
            float cB = (vl && hasB) ? b3 : 0.0f;
            float u, v;
            u = __shfl_up_sync(FULL, cA, 1);  v = __shfl_up_sync(FULL, cB, 1);
            if (lane >= 1)  { cA = fmaf(q1,  u, cA); cB = fmaf(q1,  v, cB); }
            u = __shfl_up_sync(FULL, cA, 2);  v = __shfl_up_sync(FULL, cB, 2);
            if (lane >= 2)  { cA = fmaf(q2,  u, cA); cB = fmaf(q2,  v, cB); }
            u = __shfl_up_sync(FULL, cA, 4);  v = __shfl_up_sync(FULL, cB, 4);
            if (lane >= 4)  { cA = fmaf(q4,  u, cA); cB = fmaf(q4,  v, cB); }
            u = __shfl_up_sync(FULL, cA, 8);  v = __shfl_up_sync(FULL, cB, 8);
            if (lane >= 8)  { cA = fmaf(q8,  u, cA); cB = fmaf(q8,  v, cB); }
            u = __shfl_up_sync(FULL, cA, 16); v = __shfl_up_sync(FULL, cB, 16);
            if (lane >= 16) { cA = fmaf(q16, u, cA); cB = fmaf(q16, v, cB); }

            // exclusive prefixes (single chunk: no cross-chunk carry)
            float prefA = __shfl_up_sync(FULL, cA, 1);
            float prefB = __shfl_up_sync(FULL, cB, 1);
            if (lane == 0) { prefA = 0.0f; prefB = 0.0f; }

            a0 = fmaf(prefA, w1, a0);  b0 = fmaf(prefB, w1, b0);
            a1 = fmaf(prefA, w2, a1);  b1 = fmaf(prefB, w2, b1);
            a2 = fmaf(prefA, w3, a2);  b2 = fmaf(prefB, w3, b2);
            a3 = fmaf(prefA, q,  a3);  b3 = fmaf(prefB, q,  b3);

            if (vl) {
                float e0 = oA.x - a0 * inv_tau;
                float e1 = oA.y - a1 * inv_tau;
                float e2 = oA.z - a2 * inv_tau;
                float e3 = oA.w - a3 * inv_tau;
                accA = fmaf(e0, e0, accA);
                accA = fmaf(e1, e1, accA);
                accA = fmaf(e2, e2, accA);
                accA = fmaf(e3, e3, accA);
            }
            if (vl && hasB) {
                float e0 = oB.x - b0 * inv_tau;
                float e1 = oB.y - b1 * inv_tau;
                float e2 = oB.z - b2 * inv_tau;
                float e3 = oB.w - b3 * inv_tau;
                accB = fmaf(e0, e0, accB);
                accB = fmaf(e1, e1, accB);
                accB = fmaf(e2, e2, accB);
                accB = fmaf(e3, e3, accB);
            }

            xA = nxA; xB = nxB;   // rotate pipeline
        }
        acc = accA + accB;

    } else if ((T & 3) == 0) {
        // ============ general float4 path (TV > 32) ============
        const int TV = T >> 2;
        const float w1 = decay;
        const float w2 = decay * decay;
        const float w3 = w2 * decay;
        const float q  = w2 * w2;
        const float q1  = q;
        const float q2  = q1 * q1;
        const float q4  = q2 * q2;
        const float q8  = q4 * q4;
        const float q16 = q8 * q8;
        const float qlane = __powf(q, (float)lane);

        const long long stride2 = (long long)warps_total * 2;
        for (long long p = (long long)warp_id * 2; p < pixels; p += stride2) {
            const bool hasB = (p + 1 < pixels);
            const float4* tg = (const float4*)(target  + p * (long long)T);
            const float4* ob = (const float4*)(outputs + p * (long long)T);

            float carryA = 0.0f, carryB = 0.0f;
            for (int c4 = 0; c4 < TV; c4 += 32) {
                const int  l4     = c4 + lane;
                const bool validA = (l4 < TV);
                const bool validB = validA && hasB;
                const bool more   = (c4 + 32 < TV);
                const int  last   = more ? 31 : (TV - c4 - 1);

                const float4 z = make_float4(0.f, 0.f, 0.f, 0.f);
                float4 xA = validA ? __ldcs(tg + l4)      : z;
                float4 oA = validA ? __ldcs(ob + l4)      : z;
                float4 xB = validB ? __ldcs(tg + l4 + TV) : z;
                float4 oB = validB ? __ldcs(ob + l4 + TV) : z;

                float a0 = xA.x,                  b0 = xB.x;
                float a1 = fmaf(decay, a0, xA.y), b1 = fmaf(decay, b0, xB.y);
                float a2 = fmaf(decay, a1, xA.z), b2 = fmaf(decay, b1, xB.z);
                float a3 = fmaf(decay, a2, xA.w), b3 = fmaf(decay, b2, xB.w);

                float cA = validA ? a3 : 0.0f;
                float cB = validB ? b3 : 0.0f;
                float u, v;
                u = __shfl_up_sync(FULL, cA, 1);  v = __shfl_up_sync(FULL, cB, 1);
                if (lane >= 1)  { cA = fmaf(q1,  u, cA); cB = fmaf(q1,  v, cB); }
                u = __shfl_up_sync(FULL, cA, 2);  v = __shfl_up_sync(FULL, cB, 2);
                if (lane >= 2)  { cA = fmaf(q2,  u, cA); cB = fmaf(q2,  v, cB); }
                u = __shfl_up_sync(FULL, cA, 4);  v = __shfl_up_sync(FULL, cB, 4);
                if (lane >= 4)  { cA = fmaf(q4,  u, cA); cB = fmaf(q4,  v, cB); }
                u = __shfl_up_sync(FULL, cA, 8);  v = __shfl_up_sync(FULL, cB, 8);
                if (lane >= 8)  { cA = fmaf(q8,  u, cA); cB = fmaf(q8,  v, cB); }
                u = __shfl_up_sync(FULL, cA, 16); v = __shfl_up_sync(FULL, cB, 16);
                if (lane >= 16) { cA = fmaf(q16, u, cA); cB = fmaf(q16, v, cB); }

                float prefA = __shfl_up_sync(FULL, cA, 1);
                float prefB = __shfl_up_sync(FULL, cB, 1);
                if (lane == 0) { prefA = 0.0f; prefB = 0.0f; }
                prefA = fmaf(carryA, qlane, prefA);
                prefB = fmaf(carryB, qlane, prefB);

                a0 = fmaf(prefA, w1, a0);  b0 = fmaf(prefB, w1, b0);
                a1 = fmaf(prefA, w2, a1);  b1 = fmaf(prefB, w2, b1);
                a2 = fmaf(prefA, w3, a2);  b2 = fmaf(prefB, w3, b2);
                a3 = fmaf(prefA, q,  a3);  b3 = fmaf(prefB, q,  b3);

                if (validA) {
                    float e0 = oA.x - a0 * inv_tau;
                    float e1 = oA.y - a1 * inv_tau;
                    float e2 = oA.z - a2 * inv_tau;
                    float e3 = oA.w - a3 * inv_tau;
                    acc = fmaf(e0, e0, acc); acc = fmaf(e1, e1, acc);
                    acc = fmaf(e2, e2, acc); acc = fmaf(e3, e3, acc);
                }
                if (validB) {
                    float e0 = oB.x - b0 * inv_tau;
                    float e1 = oB.y - b1 * inv_tau;
                    float e2 = oB.z - b2 * inv_tau;
                    float e3 = oB.w - b3 * inv_tau;
                    acc = fmaf(e0, e0, acc); acc = fmaf(e1, e1, acc);
                    acc = fmaf(e2, e2, acc); acc = fmaf(e3, e3, acc);
                }
                if (more) {
                    carryA = __shfl_sync(FULL, a3, last);
                    carryB = __shfl_sync(FULL, b3, last);
                }
            }
        }
    } else {
        // ============ generic scalar fallback ============
        const float d1  = decay;
        const float d2  = d1 * d1;
        const float d4  = d2 * d2;
        const float d8  = d4 * d4;
        const float d16 = d8 * d8;
        const float dlane1 = __powf(decay, (float)(lane + 1));

        for (long long p = warp_id; p < pixels; p += warps_total) {
            const float* tg = target  + p * (long long)T;
            const float* ob = outputs + p * (long long)T;
            float carry = 0.0f;
            for (int t0 = 0; t0 < T; t0 += 32) {
                const int  t     = t0 + lane;
                const bool valid = (t < T);
                float x = valid ? __ldcs(tg + t) : 0.0f;
                float o = valid ? __ldcs(ob + t) : 0.0f;
                float syn = x, v;
                v = __shfl_up_sync(FULL, syn, 1);  if (lane >= 1)  syn = fmaf(d1,  v, syn);
                v = __shfl_up_sync(FULL, syn, 2);  if (lane >= 2)  syn = fmaf(d2,  v, syn);
                v = __shfl_up_sync(FULL, syn, 4);  if (lane >= 4)  syn = fmaf(d4,  v, syn);
                v = __shfl_up_sync(FULL, syn, 8);  if (lane >= 8)  syn = fmaf(d8,  v, syn);
                v = __shfl_up_sync(FULL, syn, 16); if (lane >= 16) syn = fmaf(d16, v, syn);
                syn = fmaf(carry, dlane1, syn);
                if (valid) {
                    const float d = o - syn * inv_tau;
                    acc = fmaf(d, d, acc);
                }
                carry = __shfl_sync(FULL, syn, 31);
            }
        }
    }

    // ---- block reduction of acc ----
    #pragma unroll
    for (int off = 16; off; off >>= 1)
        acc += __shfl_down_sync(FULL, acc, off);

    __shared__ float warp_sums[8];
    __shared__ bool  s_is_last;
    const int wib = threadIdx.x >> 5;
    if (lane == 0) warp_sums[wib] = acc;
    __syncthreads();

    if (threadIdx.x == 0) {
        const int nw = blockDim.x >> 5;
        float s = 0.0f;
        #pragma unroll
        for (int i = 0; i < 8; i++)
            if (i < nw) s += warp_sums[i];
        g_partials[blockIdx.x] = s;
        __threadfence();
        unsigned old = atomicAdd(&g_ticket, 1u);
        s_is_last = (old == gridDim.x - 1);
    }
    __syncthreads();

    if (s_is_last) {
        volatile float* parts = g_partials;
        double s = 0.0;
        for (int i = threadIdx.x; i < (int)gridDim.x; i += blockDim.x)
            s += (double)parts[i];
        #pragma unroll
        for (int off = 16; off; off >>= 1)
            s += __shfl_down_sync(FULL, s, off);

        __shared__ double dsums[8];
        if (lane == 0) dsums[wib] = s;
        __syncthreads();
        if (threadIdx.x == 0) {
            const int nw = blockDim.x >> 5;
            double t = 0.0;
            #pragma unroll
            for (int i = 0; i < 8; i++)
                if (i < nw) t += dsums[i];
            out[0] = (float)(0.5 * t);
            g_ticket = 0;
        }
    }
}

extern "C" void kernel_launch(void* const* d_in, const int* in_sizes, int n_in,
                              void* d_out, int out_size)
{
    const float* outputs = (const float*)d_in[0];
    const float* target  = (const float*)d_in[1];
    const int*   n_steps = (const int*)d_in[2];
    const int*   tau_s   = (const int*)d_in[3];
    float*       out     = (float*)d_out;

    const long long n_total = (long long)in_sizes[0];

    const int threads = 256;
    const int blocks  = 148 * 8;   // 1184 <= MAX_BLOCKS; 2 full waves at 4 blocks/SM
    spike_loss_kernel<<<blocks, threads>>>(outputs, target, n_steps, tau_s, n_total, out);
}

// round 14
// speedup vs baseline: 1.0525x; 1.0187x over previous
#include <cuda_runtime.h>

#define MAX_BLOCKS 2048
__device__ float        g_partials[MAX_BLOCKS];
__device__ unsigned int g_ticket;          // 0 at load; last block resets to 0 each launch

// ---------------------------------------------------------------------------
// Loss = 0.5 * sum( (outputs - psp(target))^2 ), psp = leaky integrator over
// contiguous trailing axis T. One warp per pixel pair (lane l owns float4 of
// t=4l..4l+3); 2 adjacent pixels per warp iteration. Fast path for TV<=32:
// single straight-line chunk, software-pipelined p-loop (next iteration's
// target rows prefetched before the current scan). All global loads use
// __ldcs (read-once streaming). R12 evidence: three staging architectures all
// pin DRAM at ~73% -> platform ceiling; structure frozen at best variant.
// R14: grid = one full wave (148*4 @ 4 blocks/SM) — no wave transition,
// half-size tail reduction. Last-block reduction; single launch.
// ---------------------------------------------------------------------------
__global__ void __launch_bounds__(256, 4) spike_loss_kernel(
    const float* __restrict__ outputs,
    const float* __restrict__ target,
    const int* __restrict__ n_steps_p,
    const int* __restrict__ tau_p,
    long long n_total,
    float* __restrict__ out)
{
    const int   T       = *n_steps_p;
    const float tau     = (float)(*tau_p);
    const float inv_tau = 1.0f / tau;
    const float decay   = 1.0f - inv_tau;

    const int lane = threadIdx.x & 31;
    const unsigned FULL = 0xffffffffu;

    const long long pixels      = n_total / (long long)T;
    const int       warps_total = (gridDim.x * blockDim.x) >> 5;
    const int       warp_id     = (int)((blockIdx.x * blockDim.x + threadIdx.x) >> 5);

    float acc = 0.0f;

    if ((T & 3) == 0 && (T >> 2) <= 32) {
        // ============ fast path: TV <= 32, single chunk, pipelined ============
        const int TV = T >> 2;

        const float w1 = decay;
        const float w2 = decay * decay;
        const float w3 = w2 * decay;
        const float q  = w2 * w2;              // decay^4 (warp-scan ratio)
        const float q1  = q;
        const float q2  = q1 * q1;
        const float q4  = q2 * q2;
        const float q8  = q4 * q4;
        const float q16 = q8 * q8;

        const float4 z = make_float4(0.f, 0.f, 0.f, 0.f);
        const bool   vl = (lane < TV);
        const long long stride2 = (long long)warps_total * 2;

        float accA = 0.0f, accB = 0.0f;

        long long p = (long long)warp_id * 2;

        // prologue: preload target rows for first iteration (streaming loads)
        float4 xA = z, xB = z;
        if (p < pixels) {
            const float4* tg = (const float4*)(target + p * (long long)T);
            const bool hasB0 = (p + 1 < pixels);
            if (vl)          xA = __ldcs(tg + lane);
            if (vl && hasB0) xB = __ldcs(tg + lane + TV);
        }

        for (; p < pixels; p += stride2) {
            const bool hasB = (p + 1 < pixels);

            // outputs for current iteration: consumed only at the loss (big slack)
            const float4* ob = (const float4*)(outputs + p * (long long)T);
            float4 oA = vl           ? __ldcs(ob + lane)      : z;
            float4 oB = (vl && hasB) ? __ldcs(ob + lane + TV) : z;

            // prefetch target rows for NEXT iteration (overlaps the scan below)
            const long long pn = p + stride2;
            float4 nxA = z, nxB = z;
            if (pn < pixels) {
                const float4* tgn = (const float4*)(target + pn * (long long)T);
                const bool hasBn = (pn + 1 < pixels);
                if (vl)          nxA = __ldcs(tgn + lane);
                if (vl && hasBn) nxB = __ldcs(tgn + lane + TV);
            }

            // local 4-elem inclusive scans (two independent chains)
            float a0 = xA.x,                  b0 = xB.x;
            float a1 = fmaf(decay, a0, xA.y), b1 = fmaf(decay, b0, xB.y);
            float a2 = fmaf(decay, a1, xA.z), b2 = fmaf(decay, b1, xB.z);
            float a3 = fmaf(decay, a2, xA.w), b3 = fmaf(decay, b2, xB.w);

            // interleaved Kogge-Stone warp scans of lane carries (ratio q)
            float cA = vl ? a3 : 0.0f;
            float cB = (vl && hasB) ? b3 : 0.0f;
            float u, v;
            u = __shfl_up_sync(FULL, cA, 1);  v = __shfl_up_sync(FULL, cB, 1);
            if (lane >= 1)  { cA = fmaf(q1,  u, cA); cB = fmaf(q1,  v, cB); }
            u = __shfl_up_sync(FULL, cA, 2);  v = __shfl_up_sync(FULL, cB, 2);
            if (lane >= 2)  { cA = fmaf(q2,  u, cA); cB = fmaf(q2,  v, cB); }
            u = __shfl_up_sync(FULL, cA, 4);  v = __shfl_up_sync(FULL, cB, 4);
            if (lane >= 4)  { cA = fmaf(q4,  u, cA); cB = fmaf(q4,  v, cB); }
            u = __shfl_up_sync(FULL, cA, 8);  v = __shfl_up_sync(FULL, cB, 8);
            if (lane >= 8)  { cA = fmaf(q8,  u, cA); cB = fmaf(q8,  v, cB); }
            u = __shfl_up_sync(FULL, cA, 16); v = __shfl_up_sync(FULL, cB, 16);
            if (lane >= 16) { cA = fmaf(q16, u, cA); cB = fmaf(q16, v, cB); }

            // exclusive prefixes (single chunk: no cross-chunk carry)
            float prefA = __shfl_up_sync(FULL, cA, 1);
            float prefB = __shfl_up_sync(FULL, cB, 1);
            if (lane == 0) { prefA = 0.0f; prefB = 0.0f; }

            a0 = fmaf(prefA, w1, a0);  b0 = fmaf(prefB, w1, b0);
            a1 = fmaf(prefA, w2, a1);  b1 = fmaf(prefB, w2, b1);
            a2 = fmaf(prefA, w3, a2);  b2 = fmaf(prefB, w3, b2);
            a3 = fmaf(prefA, q,  a3);  b3 = fmaf(prefB, q,  b3);

            if (vl) {
                float e0 = oA.x - a0 * inv_tau;
                float e1 = oA.y - a1 * inv_tau;
                float e2 = oA.z - a2 * inv_tau;
                float e3 = oA.w - a3 * inv_tau;
                accA = fmaf(e0, e0, accA);
                accA = fmaf(e1, e1, accA);
                accA = fmaf(e2, e2, accA);
                accA = fmaf(e3, e3, accA);
            }
            if (vl && hasB) {
                float e0 = oB.x - b0 * inv_tau;
                float e1 = oB.y - b1 * inv_tau;
                float e2 = oB.z - b2 * inv_tau;
                float e3 = oB.w - b3 * inv_tau;
                accB = fmaf(e0, e0, accB);
                accB = fmaf(e1, e1, accB);
                accB = fmaf(e2, e2, accB);
                accB = fmaf(e3, e3, accB);
            }

            xA = nxA; xB = nxB;   // rotate pipeline
        }
        acc = accA + accB;

    } else if ((T & 3) == 0) {
        // ============ general float4 path (TV > 32) ============
        const int TV = T >> 2;
        const float w1 = decay;
        const float w2 = decay * decay;
        const float w3 = w2 * decay;
        const float q  = w2 * w2;
        const float q1  = q;
        const float q2  = q1 * q1;
        const float q4  = q2 * q2;
        const float q8  = q4 * q4;
        const float q16 = q8 * q8;
        const float qlane = __powf(q, (float)lane);

        const long long stride2 = (long long)warps_total * 2;
        for (long long p = (long long)warp_id * 2; p < pixels; p += stride2) {
            const bool hasB = (p + 1 < pixels);
            const float4* tg = (const float4*)(target  + p * (long long)T);
            const float4* ob = (const float4*)(outputs + p * (long long)T);

            float carryA = 0.0f, carryB = 0.0f;
            for (int c4 = 0; c4 < TV; c4 += 32) {
                const int  l4     = c4 + lane;
                const bool validA = (l4 < TV);
                const bool validB = validA && hasB;
                const bool more   = (c4 + 32 < TV);
                const int  last   = more ? 31 : (TV - c4 - 1);

                const float4 z = make_float4(0.f, 0.f, 0.f, 0.f);
                float4 xA = validA ? __ldcs(tg + l4)      : z;
                float4 oA = validA ? __ldcs(ob + l4)      : z;
                float4 xB = validB ? __ldcs(tg + l4 + TV) : z;
                float4 oB = validB ? __ldcs(ob + l4 + TV) : z;

                float a0 = xA.x,                  b0 = xB.x;
                float a1 = fmaf(decay, a0, xA.y), b1 = fmaf(decay, b0, xB.y);
                float a2 = fmaf(decay, a1, xA.z), b2 = fmaf(decay, b1, xB.z);
                float a3 = fmaf(decay, a2, xA.w), b3 = fmaf(decay, b2, xB.w);

                float cA = validA ? a3 : 0.0f;
                float cB = validB ? b3 : 0.0f;
                float u, v;
                u = __shfl_up_sync(FULL, cA, 1);  v = __shfl_up_sync(FULL, cB, 1);
                if (lane >= 1)  { cA = fmaf(q1,  u, cA); cB = fmaf(q1,  v, cB); }
                u = __shfl_up_sync(FULL, cA, 2);  v = __shfl_up_sync(FULL, cB, 2);
                if (lane >= 2)  { cA = fmaf(q2,  u, cA); cB = fmaf(q2,  v, cB); }
                u = __shfl_up_sync(FULL, cA, 4);  v = __shfl_up_sync(FULL, cB, 4);
                if (lane >= 4)  { cA = fmaf(q4,  u, cA); cB = fmaf(q4,  v, cB); }
                u = __shfl_up_sync(FULL, cA, 8);  v = __shfl_up_sync(FULL, cB, 8);
                if (lane >= 8)  { cA = fmaf(q8,  u, cA); cB = fmaf(q8,  v, cB); }
                u = __shfl_up_sync(FULL, cA, 16); v = __shfl_up_sync(FULL, cB, 16);
                if (lane >= 16) { cA = fmaf(q16, u, cA); cB = fmaf(q16, v, cB); }

                float prefA = __shfl_up_sync(FULL, cA, 1);
                float prefB = __shfl_up_sync(FULL, cB, 1);
                if (lane == 0) { prefA = 0.0f; prefB = 0.0f; }
                prefA = fmaf(carryA, qlane, prefA);
                prefB = fmaf(carryB, qlane, prefB);

                a0 = fmaf(prefA, w1, a0);  b0 = fmaf(prefB, w1, b0);
                a1 = fmaf(prefA, w2, a1);  b1 = fmaf(prefB, w2, b1);
                a2 = fmaf(prefA, w3, a2);  b2 = fmaf(prefB, w3, b2);
                a3 = fmaf(prefA, q,  a3);  b3 = fmaf(prefB, q,  b3);

                if (validA) {
                    float e0 = oA.x - a0 * inv_tau;
                    float e1 = oA.y - a1 * inv_tau;
                    float e2 = oA.z - a2 * inv_tau;
                    float e3 = oA.w - a3 * inv_tau;
                    acc = fmaf(e0, e0, acc); acc = fmaf(e1, e1, acc);
                    acc = fmaf(e2, e2, acc); acc = fmaf(e3, e3, acc);
                }
                if (validB) {
                    float e0 = oB.x - b0 * inv_tau;
                    float e1 = oB.y - b1 * inv_tau;
                    float e2 = oB.z - b2 * inv_tau;
                    float e3 = oB.w - b3 * inv_tau;
                    acc = fmaf(e0, e0, acc); acc = fmaf(e1, e1, acc);
                    acc = fmaf(e2, e2, acc); acc = fmaf(e3, e3, acc);
                }
                if (more) {
                    carryA = __shfl_sync(FULL, a3, last);
                    carryB = __shfl_sync(FULL, b3, last);
                }
            }
        }
    } else {
        // ============ generic scalar fallback ============
        const float d1  = decay;
        const float d2  = d1 * d1;
        const float d4  = d2 * d2;
        const float d8  = d4 * d4;
        const float d16 = d8 * d8;
        const float dlane1 = __powf(decay, (float)(lane + 1));

        for (long long p = warp_id; p < pixels; p += warps_total) {
            const float* tg = target  + p * (long long)T;
            const float* ob = outputs + p * (long long)T;
            float carry = 0.0f;
            for (int t0 = 0; t0 < T; t0 += 32) {
                const int  t     = t0 + lane;
                const bool valid = (t < T);
                float x = valid ? __ldcs(tg + t) : 0.0f;
                float o = valid ? __ldcs(ob + t) : 0.0f;
                float syn = x, v;
                v = __shfl_up_sync(FULL, syn, 1);  if (lane >= 1)  syn = fmaf(d1,  v, syn);
                v = __shfl_up_sync(FULL, syn, 2);  if (lane >= 2)  syn = fmaf(d2,  v, syn);
                v = __shfl_up_sync(FULL, syn, 4);  if (lane >= 4)  syn = fmaf(d4,  v, syn);
                v = __shfl_up_sync(FULL, syn, 8);  if (lane >= 8)  syn = fmaf(d8,  v, syn);
                v = __shfl_up_sync(FULL, syn, 16); if (lane >= 16) syn = fmaf(d16, v, syn);
                syn = fmaf(carry, dlane1, syn);
                if (valid) {
                    const float d = o - syn * inv_tau;
                    acc = fmaf(d, d, acc);
                }
                carry = __shfl_sync(FULL, syn, 31);
            }
        }
    }

    // ---- block reduction of acc ----
    #pragma unroll
    for (int off = 16; off; off >>= 1)
        acc += __shfl_down_sync(FULL, acc, off);

    __shared__ float warp_sums[8];
    __shared__ bool  s_is_last;
    const int wib = threadIdx.x >> 5;
    if (lane == 0) warp_sums[wib] = acc;
    __syncthreads();

    if (threadIdx.x == 0) {
        const int nw = blockDim.x >> 5;
        float s = 0.0f;
        #pragma unroll
        for (int i = 0; i < 8; i++)
            if (i < nw) s += warp_sums[i];
        g_partials[blockIdx.x] = s;
        __threadfence();
        unsigned old = atomicAdd(&g_ticket, 1u);
        s_is_last = (old == gridDim.x - 1);
    }
    __syncthreads();

    if (s_is_last) {
        volatile float* parts = g_partials;
        double s = 0.0;
        for (int i = threadIdx.x; i < (int)gridDim.x; i += blockDim.x)
            s += (double)parts[i];
        #pragma unroll
        for (int off = 16; off; off >>= 1)
            s += __shfl_down_sync(FULL, s, off);

        __shared__ double dsums[8];
        if (lane == 0) dsums[wib] = s;
        __syncthreads();
        if (threadIdx.x == 0) {
            const int nw = blockDim.x >> 5;
            double t = 0.0;
            #pragma unroll
            for (int i = 0; i < 8; i++)
                if (i < nw) t += dsums[i];
            out[0] = (float)(0.5 * t);
            g_ticket = 0;
        }
    }
}

extern "C" void kernel_launch(void* const* d_in, const int* in_sizes, int n_in,
                              void* d_out, int out_size)
{
    const float* outputs = (const float*)d_in[0];
    const float* target  = (const float*)d_in[1];
    const int*   n_steps = (const int*)d_in[2];
    const int*   tau_s   = (const int*)d_in[3];
    float*       out     = (float*)d_out;

    const long long n_total = (long long)in_sizes[0];

    const int threads = 256;
    const int blocks  = 148 * 4;   // 592: exactly ONE full wave at 4 blocks/SM
    spike_loss_kernel<<<blocks, threads>>>(outputs, target, n_steps, tau_s, n_total, out);
}